// round 3
// baseline (speedup 1.0000x reference)
#include <cuda_runtime.h>
#include <math.h>
#include <stdint.h>

#define NN 200000
#define EE 6400000
#define IND 128
#define DD 16
#define GG 1024
#define BN_EPS 1e-5f

// ---------------- device scratch (no allocs allowed) ----------------
__device__ float g_h[NN * DD];     // h = x @ W (pre-bias)
__device__ float g_hh[NN * DD];    // hh = h * dis[row]
__device__ float g_x1[NN * DD];    // layer activation buffer
__device__ int   g_cnt[NN];        // in-degree (col counts)
__device__ int   g_off[NN];        // bucket start
__device__ int   g_cur[NN];        // bucket cursor
__device__ float g_dis[NN];        // rsqrt(deg+1)
__device__ int   g_srcbuf[EE];     // src node per edge, bucketed by dst
__device__ int   g_total;
__device__ int   g_gstart[GG];
__device__ int   g_gend[GG];
__device__ float g_gmax[GG * DD];
__device__ float g_gsum[GG * DD];

// TF32 rounding to match XLA/cuBLAS default f32 matmul precision on GPU
__device__ __forceinline__ float tf32r(float a) {
    uint32_t u;
    asm("cvt.rna.tf32.f32 %0, %1;" : "=r"(u) : "f"(a));
    return __uint_as_float(u);
}

// ---------------- kernels ----------------

__global__ void k_init() {
    int i = blockIdx.x * blockDim.x + threadIdx.x;
    if (i < NN) g_cnt[i] = 0;
    if (i < GG) { g_gstart[i] = NN; g_gend[i] = -1; }
    if (i == 0) g_total = 0;
}

__global__ void k_count(const int* __restrict__ col) {
    int e = blockIdx.x * blockDim.x + threadIdx.x;
    if (e < EE) atomicAdd(&g_cnt[col[e]], 1);
}

__global__ void k_offsets() {
    int i = blockIdx.x * blockDim.x + threadIdx.x;
    if (i < NN) {
        int c = g_cnt[i];
        int o = atomicAdd(&g_total, c);   // bucket order irrelevant
        g_off[i] = o;
        g_cur[i] = o;
        g_dis[i] = rsqrtf((float)c + 1.0f);
    }
}

__global__ void k_fill(const int* __restrict__ row, const int* __restrict__ col) {
    int e = blockIdx.x * blockDim.x + threadIdx.x;
    if (e < EE) {
        int c = col[e];
        int p = atomicAdd(&g_cur[c], 1);
        g_srcbuf[p] = row[e];
    }
}

// h = x @ W1 (200000x128 @ 128x16) in TF32-emulated math; also hh = h * dis
__global__ void k_gemm1(const float* __restrict__ x, const float* __restrict__ W1) {
    __shared__ __align__(16) float sW[IND * DD];   // 8 KB (tf32-rounded)
    __shared__ float sx[64][IND + 1];              // 33 KB (tf32-rounded)
    int t = threadIdx.x;
    for (int i = t; i < IND * DD; i += 256) sW[i] = tf32r(W1[i]);
    int base = blockIdx.x * 64;
    for (int i = t; i < 64 * 32; i += 256) {
        int r = i >> 5, c4 = i & 31;
        int gr = base + r;
        float4 v = (gr < NN) ? ((const float4*)x)[(size_t)gr * 32 + c4]
                             : make_float4(0.f, 0.f, 0.f, 0.f);
        sx[r][c4 * 4 + 0] = tf32r(v.x); sx[r][c4 * 4 + 1] = tf32r(v.y);
        sx[r][c4 * 4 + 2] = tf32r(v.z); sx[r][c4 * 4 + 3] = tf32r(v.w);
    }
    __syncthreads();
    int nl = t >> 2, part = t & 3;
    int n = base + nl;
    if (n >= NN) return;
    float4 acc = make_float4(0.f, 0.f, 0.f, 0.f);
    const float4* W4 = (const float4*)sW;
    #pragma unroll 16
    for (int k = 0; k < IND; k++) {
        float xv = sx[nl][k];
        float4 w = W4[k * 4 + part];
        acc.x += xv * w.x; acc.y += xv * w.y;
        acc.z += xv * w.z; acc.w += xv * w.w;
    }
    float d = g_dis[n];
    ((float4*)g_h)[n * 4 + part] = acc;
    float4 s = make_float4(acc.x * d, acc.y * d, acc.z * d, acc.w * d);
    ((float4*)g_hh)[n * 4 + part] = s;
}

// gather-aggregate + self-loop + bias + relu + batchnorm -> g_x1
__global__ void k_agg(const float* __restrict__ b, const float* __restrict__ gam,
                      const float* __restrict__ bet, const float* __restrict__ mu,
                      const float* __restrict__ var) {
    int t = blockIdx.x * blockDim.x + threadIdx.x;
    int n = t >> 2, part = t & 3;
    if (n >= NN) return;
    int o = g_off[n], c = g_cnt[n];
    float4 acc = make_float4(0.f, 0.f, 0.f, 0.f);
    const float4* hh4 = (const float4*)g_hh;
    for (int e = o; e < o + c; e++) {
        int s = __ldg(&g_srcbuf[e]);
        float4 vv = hh4[s * 4 + part];
        acc.x += vv.x; acc.y += vv.y; acc.z += vv.z; acc.w += vv.w;
    }
    float d = g_dis[n];
    float d2 = d * d;
    float4 hv = ((const float4*)g_h)[n * 4 + part];
    int f = part * 4;
    float r[4];
    r[0] = acc.x * d + hv.x * d2 + b[f + 0];
    r[1] = acc.y * d + hv.y * d2 + b[f + 1];
    r[2] = acc.z * d + hv.z * d2 + b[f + 2];
    r[3] = acc.w * d + hv.w * d2 + b[f + 3];
    float4 ov;
    float* op = &ov.x;
    #pragma unroll
    for (int j = 0; j < 4; j++) {
        float v = fmaxf(r[j], 0.f);
        op[j] = (v - mu[f + j]) * rsqrtf(var[f + j] + BN_EPS) * gam[f + j] + bet[f + j];
    }
    ((float4*)g_x1)[n * 4 + part] = ov;
}

// h = x1 @ W2 (16x16) in TF32-emulated math; hh = h * dis
__global__ void k_gemm2(const float* __restrict__ W2) {
    __shared__ float sW[DD * DD];
    int t = threadIdx.x;
    if (t < DD * DD) sW[t] = tf32r(W2[t]);
    __syncthreads();
    int n = blockIdx.x * blockDim.x + t;
    if (n >= NN) return;
    const float4* xr = (const float4*)(g_x1 + (size_t)n * DD);
    float4 q0 = xr[0], q1 = xr[1], q2 = xr[2], q3 = xr[3];
    float xv[16] = { q0.x,q0.y,q0.z,q0.w, q1.x,q1.y,q1.z,q1.w,
                     q2.x,q2.y,q2.z,q2.w, q3.x,q3.y,q3.z,q3.w };
    #pragma unroll
    for (int k = 0; k < 16; k++) xv[k] = tf32r(xv[k]);
    float acc[16];
    #pragma unroll
    for (int j = 0; j < 16; j++) acc[j] = 0.f;
    #pragma unroll
    for (int k = 0; k < 16; k++) {
        float xk = xv[k];
        #pragma unroll
        for (int j = 0; j < 16; j++) acc[j] += xk * sW[k * 16 + j];
    }
    float d = g_dis[n];
    float4* ho = (float4*)(g_h + (size_t)n * DD);
    float4* so = (float4*)(g_hh + (size_t)n * DD);
    #pragma unroll
    for (int q = 0; q < 4; q++) {
        float4 hv = make_float4(acc[q*4+0], acc[q*4+1], acc[q*4+2], acc[q*4+3]);
        ho[q] = hv;
        so[q] = make_float4(hv.x * d, hv.y * d, hv.z * d, hv.w * d);
    }
}

__global__ void k_bounds(const int* __restrict__ batch) {
    int i = blockIdx.x * blockDim.x + threadIdx.x;
    if (i < NN) {
        int bb = batch[i];
        atomicMin(&g_gstart[bb], i);
        atomicMax(&g_gend[bb], i);
    }
}

__global__ void k_pool() {
    int t = blockIdx.x * blockDim.x + threadIdx.x;
    if (t >= GG * DD) return;
    int gI = t >> 4, f = t & 15;
    int s = g_gstart[gI], e = g_gend[gI];
    float mx = -INFINITY, sm = 0.f;
    for (int n = s; n <= e; n++) {
        float vv = g_x1[(size_t)n * DD + f];
        mx = fmaxf(mx, vv);
        sm += vv;
    }
    g_gmax[t] = mx;
    g_gsum[t] = sm;
}

__global__ void k_head(const float* __restrict__ Wb, const float* __restrict__ bb,
                       const float* __restrict__ Wm, const float* __restrict__ bm,
                       float* __restrict__ out) {
    __shared__ float sWb[32 * 16];
    __shared__ float sbb[16];
    __shared__ float sWm[16];
    __shared__ float sbm;
    int t = threadIdx.x;
    for (int i = t; i < 32 * 16; i += 256) sWb[i] = tf32r(Wb[i]);
    if (t < 16) { sbb[t] = bb[t]; sWm[t] = tf32r(Wm[t]); }
    if (t == 0) sbm = bm[0];
    __syncthreads();
    int gI = blockIdx.x * blockDim.x + t;
    if (gI >= GG) return;
    float inp[32];
    float cntf = (float)(g_gend[gI] - g_gstart[gI] + 1);
    float inv = 1.f / cntf;
    #pragma unroll
    for (int f = 0; f < 16; f++) {
        inp[f] = tf32r(g_gmax[gI * 16 + f]);
        inp[16 + f] = tf32r(g_gsum[gI * 16 + f] * inv);
    }
    float acc = sbm;
    #pragma unroll
    for (int j = 0; j < 16; j++) {
        float tt = sbb[j];
        #pragma unroll
        for (int i = 0; i < 32; i++) tt += inp[i] * sWb[i * 16 + j];
        tt = fmaxf(tt, 0.f);
        acc += tf32r(tt) * sWm[j];
    }
    out[gI] = 1.f / (1.f + expf(-acc));
}

// ---------------- launch ----------------
extern "C" void kernel_launch(void* const* d_in, const int* in_sizes, int n_in,
                              void* d_out, int out_size) {
    const float* x   = (const float*)d_in[0];
    const int*   ei  = (const int*)d_in[1];      // [2, E]
    const int*   bat = (const int*)d_in[2];
    const float* W1  = (const float*)d_in[3];
    const float* b1  = (const float*)d_in[4];
    const float* g1  = (const float*)d_in[5];
    const float* be1 = (const float*)d_in[6];
    const float* m1  = (const float*)d_in[7];
    const float* v1  = (const float*)d_in[8];
    const float* W2  = (const float*)d_in[9];
    const float* b2  = (const float*)d_in[10];
    const float* g2  = (const float*)d_in[11];
    const float* be2 = (const float*)d_in[12];
    const float* m2  = (const float*)d_in[13];
    const float* v2  = (const float*)d_in[14];
    const float* Wb  = (const float*)d_in[15];
    const float* bb  = (const float*)d_in[16];
    const float* Wm  = (const float*)d_in[17];
    const float* bm  = (const float*)d_in[18];
    float* out = (float*)d_out;

    const int* row = ei;
    const int* col = ei + EE;

    int nb_n  = (NN + 255) / 256;        // 782
    int nb_e  = (EE + 255) / 256;        // 25000
    int nb_4n = (NN * 4 + 255) / 256;    // 3125
    int nb_g1 = NN / 64;                 // 3125

    k_init<<<nb_n, 256>>>();
    k_count<<<nb_e, 256>>>(col);
    k_offsets<<<nb_n, 256>>>();
    k_fill<<<nb_e, 256>>>(row, col);

    k_gemm1<<<nb_g1, 256>>>(x, W1);
    k_agg<<<nb_4n, 256>>>(b1, g1, be1, m1, v1);
    k_gemm2<<<nb_n, 256>>>(W2);
    k_agg<<<nb_4n, 256>>>(b2, g2, be2, m2, v2);

    k_bounds<<<nb_n, 256>>>(bat);
    k_pool<<<(GG * DD + 255) / 256, 256>>>();
    k_head<<<(GG + 255) / 256, 256>>>(Wb, bb, Wm, bm, out);
}

// round 5
// speedup vs baseline: 1.1224x; 1.1224x over previous
#include <cuda_runtime.h>
#include <cuda_fp16.h>
#include <math.h>
#include <stdint.h>

#define NN 200000
#define EE 6400000
#define IND 128
#define DD 16
#define GG 1024
#define BN_EPS 1e-5f

// ---------------- device scratch (no allocs allowed) ----------------
__device__ float g_h[NN * DD];                 // h (pre-bias), fp32; reused for layer2
__device__ __align__(16) uint4 g_hh1[NN * 2];  // fp16 hh layer1: node n -> 2 uint4 (16 halves)
__device__ __align__(16) uint4 g_hh2[NN * 2];  // fp16 hh layer2
__device__ float g_x2[NN * DD];                // layer-2 activation (pool input)
__device__ int   g_cnt[NN];
__device__ int   g_off[NN];
__device__ int   g_cur[NN];
__device__ float g_dis[NN];
__device__ int   g_srcbuf[EE];
__device__ int   g_total;
__device__ int   g_gstart[GG];
__device__ int   g_gend[GG];
__device__ float g_gmax[GG * DD];
__device__ float g_gsum[GG * DD];

// TF32 rounding to match XLA default f32 matmul precision on GPU
__device__ __forceinline__ float tf32r(float a) {
    uint32_t u;
    asm("cvt.rna.tf32.f32 %0, %1;" : "=r"(u) : "f"(a));
    return __uint_as_float(u);
}

// half2 <-> u32 bit casts (register views, zero instructions)
__device__ __forceinline__ unsigned h2u(__half2 h) {
    return *reinterpret_cast<unsigned*>(&h);
}
__device__ __forceinline__ __half2 u2h(unsigned u) {
    return *reinterpret_cast<__half2*>(&u);
}

// ---------------- CSR build ----------------

__global__ void k_init() {
    int i = blockIdx.x * blockDim.x + threadIdx.x;
    if (i < NN) g_cnt[i] = 0;
    if (i == 0) g_total = 0;
}

__global__ void k_count(const int* __restrict__ col) {
    int e4 = blockIdx.x * blockDim.x + threadIdx.x;
    if (e4 < EE / 4) {
        int4 c = ((const int4*)col)[e4];
        atomicAdd(&g_cnt[c.x], 1);
        atomicAdd(&g_cnt[c.y], 1);
        atomicAdd(&g_cnt[c.z], 1);
        atomicAdd(&g_cnt[c.w], 1);
    }
}

__global__ void k_offsets() {
    int i = blockIdx.x * blockDim.x + threadIdx.x;
    if (i < NN) {
        int c = g_cnt[i];
        int o = atomicAdd(&g_total, c);
        g_off[i] = o;
        g_cur[i] = o;
        g_dis[i] = rsqrtf((float)c + 1.0f);
    }
}

__global__ void k_fill(const int* __restrict__ row, const int* __restrict__ col) {
    int e4 = blockIdx.x * blockDim.x + threadIdx.x;
    if (e4 < EE / 4) {
        int4 c = ((const int4*)col)[e4];
        int4 r = ((const int4*)row)[e4];
        g_srcbuf[atomicAdd(&g_cur[c.x], 1)] = r.x;
        g_srcbuf[atomicAdd(&g_cur[c.y], 1)] = r.y;
        g_srcbuf[atomicAdd(&g_cur[c.z], 1)] = r.z;
        g_srcbuf[atomicAdd(&g_cur[c.w], 1)] = r.w;
    }
}

// ---------------- dense compute ----------------

// h = tf32(x) @ tf32(W1)  (200000x128 @ 128x16), fp32 out. No dis dependency.
__global__ void k_gemm1h(const float* __restrict__ x, const float* __restrict__ W1) {
    __shared__ __align__(16) float sW[IND * DD];
    __shared__ float sx[64][IND + 1];
    int t = threadIdx.x;
    for (int i = t; i < IND * DD; i += 256) sW[i] = tf32r(W1[i]);
    int base = blockIdx.x * 64;
    for (int i = t; i < 64 * 32; i += 256) {
        int r = i >> 5, c4 = i & 31;
        int gr = base + r;
        float4 v = (gr < NN) ? ((const float4*)x)[(size_t)gr * 32 + c4]
                             : make_float4(0.f, 0.f, 0.f, 0.f);
        sx[r][c4 * 4 + 0] = tf32r(v.x); sx[r][c4 * 4 + 1] = tf32r(v.y);
        sx[r][c4 * 4 + 2] = tf32r(v.z); sx[r][c4 * 4 + 3] = tf32r(v.w);
    }
    __syncthreads();
    int nl = t >> 2, part = t & 3;
    int n = base + nl;
    if (n >= NN) return;
    float4 acc = make_float4(0.f, 0.f, 0.f, 0.f);
    const float4* W4 = (const float4*)sW;
    #pragma unroll 16
    for (int k = 0; k < IND; k++) {
        float xv = sx[nl][k];
        float4 w = W4[k * 4 + part];
        acc.x += xv * w.x; acc.y += xv * w.y;
        acc.z += xv * w.z; acc.w += xv * w.w;
    }
    ((float4*)g_h)[n * 4 + part] = acc;
}

// hh1 = fp16(h * dis)  (needs gemm1h + offsets)
__global__ void k_hh1() {
    int t = blockIdx.x * blockDim.x + threadIdx.x;
    int n = t >> 1, p = t & 1;
    if (n >= NN) return;
    float d = g_dis[n];
    float4 a = ((const float4*)g_h)[n * 4 + p * 2];
    float4 b = ((const float4*)g_h)[n * 4 + p * 2 + 1];
    uint4 w;
    w.x = h2u(__floats2half2_rn(a.x * d, a.y * d));
    w.y = h2u(__floats2half2_rn(a.z * d, a.w * d));
    w.z = h2u(__floats2half2_rn(b.x * d, b.y * d));
    w.w = h2u(__floats2half2_rn(b.z * d, b.w * d));
    g_hh1[n * 2 + p] = w;
}

__device__ __forceinline__ void acc_uint4(float* acc, uint4 v) {
    float2 f;
    f = __half22float2(u2h(v.x)); acc[0] += f.x; acc[1] += f.y;
    f = __half22float2(u2h(v.y)); acc[2] += f.x; acc[3] += f.y;
    f = __half22float2(u2h(v.z)); acc[4] += f.x; acc[5] += f.y;
    f = __half22float2(u2h(v.w)); acc[6] += f.x; acc[7] += f.y;
}

// layer1 aggregate + bias + relu + BN1 + (x1 @ W2 fused, TF32) -> g_h (h2) + g_hh2
__global__ void k_agg1(const float* __restrict__ b1, const float* __restrict__ g1,
                       const float* __restrict__ be1, const float* __restrict__ m1,
                       const float* __restrict__ v1, const float* __restrict__ W2) {
    __shared__ float sW[DD * DD];
    int tt = threadIdx.x;
    if (tt < DD * DD) sW[tt] = tf32r(W2[tt]);
    __syncthreads();
    int t = blockIdx.x * blockDim.x + tt;
    int n = t >> 1, p = t & 1;
    if (n >= NN) return;
    int o = g_off[n], c = g_cnt[n];
    float acc[8] = {0.f, 0.f, 0.f, 0.f, 0.f, 0.f, 0.f, 0.f};
    #pragma unroll 4
    for (int e = o; e < o + c; e++) {
        int s = __ldg(&g_srcbuf[e]);
        acc_uint4(acc, __ldg(&g_hh1[s * 2 + p]));
    }
    float d = g_dis[n], d2 = d * d;
    float4 hv0 = ((const float4*)g_h)[n * 4 + p * 2];
    float4 hv1 = ((const float4*)g_h)[n * 4 + p * 2 + 1];
    float hv[8] = {hv0.x, hv0.y, hv0.z, hv0.w, hv1.x, hv1.y, hv1.z, hv1.w};
    int f0 = p * 8;
    float loc[8];
    #pragma unroll
    for (int j = 0; j < 8; j++) {
        float r = acc[j] * d + hv[j] * d2 + __ldg(&b1[f0 + j]);
        r = fmaxf(r, 0.f);
        r = (r - __ldg(&m1[f0 + j])) * rsqrtf(__ldg(&v1[f0 + j]) + BN_EPS)
            * __ldg(&g1[f0 + j]) + __ldg(&be1[f0 + j]);
        loc[j] = tf32r(r);
    }
    // exchange halves with partner thread (whole warps active: NN*2 % 32 == 0)
    float x1[16];
    #pragma unroll
    for (int j = 0; j < 8; j++) {
        float other = __shfl_xor_sync(0xFFFFFFFFu, loc[j], 1);
        x1[f0 + j] = loc[j];
        x1[(f0 ^ 8) + j] = other;
    }
    float h2[8];
    #pragma unroll
    for (int j = 0; j < 8; j++) {
        float a = 0.f;
        #pragma unroll
        for (int k = 0; k < 16; k++) a += x1[k] * sW[k * 16 + f0 + j];
        h2[j] = a;
    }
    ((float4*)g_h)[n * 4 + p * 2]     = make_float4(h2[0], h2[1], h2[2], h2[3]);
    ((float4*)g_h)[n * 4 + p * 2 + 1] = make_float4(h2[4], h2[5], h2[6], h2[7]);
    uint4 w;
    w.x = h2u(__floats2half2_rn(h2[0] * d, h2[1] * d));
    w.y = h2u(__floats2half2_rn(h2[2] * d, h2[3] * d));
    w.z = h2u(__floats2half2_rn(h2[4] * d, h2[5] * d));
    w.w = h2u(__floats2half2_rn(h2[6] * d, h2[7] * d));
    g_hh2[n * 2 + p] = w;
}

// layer2 aggregate + bias + relu + BN2 -> g_x2
__global__ void k_agg2(const float* __restrict__ b2, const float* __restrict__ g2,
                       const float* __restrict__ be2, const float* __restrict__ m2,
                       const float* __restrict__ v2) {
    int t = blockIdx.x * blockDim.x + threadIdx.x;
    int n = t >> 1, p = t & 1;
    if (n >= NN) return;
    int o = g_off[n], c = g_cnt[n];
    float acc[8] = {0.f, 0.f, 0.f, 0.f, 0.f, 0.f, 0.f, 0.f};
    #pragma unroll 4
    for (int e = o; e < o + c; e++) {
        int s = __ldg(&g_srcbuf[e]);
        acc_uint4(acc, __ldg(&g_hh2[s * 2 + p]));
    }
    float d = g_dis[n], d2 = d * d;
    float4 hv0 = ((const float4*)g_h)[n * 4 + p * 2];
    float4 hv1 = ((const float4*)g_h)[n * 4 + p * 2 + 1];
    float hv[8] = {hv0.x, hv0.y, hv0.z, hv0.w, hv1.x, hv1.y, hv1.z, hv1.w};
    int f0 = p * 8;
    float ov[8];
    #pragma unroll
    for (int j = 0; j < 8; j++) {
        float r = acc[j] * d + hv[j] * d2 + __ldg(&b2[f0 + j]);
        r = fmaxf(r, 0.f);
        ov[j] = (r - __ldg(&m2[f0 + j])) * rsqrtf(__ldg(&v2[f0 + j]) + BN_EPS)
                * __ldg(&g2[f0 + j]) + __ldg(&be2[f0 + j]);
    }
    ((float4*)g_x2)[n * 4 + p * 2]     = make_float4(ov[0], ov[1], ov[2], ov[3]);
    ((float4*)g_x2)[n * 4 + p * 2 + 1] = make_float4(ov[4], ov[5], ov[6], ov[7]);
}

// ---------------- pooling + head ----------------

// batch is sorted: boundary detection, no atomics
__global__ void k_bounds(const int* __restrict__ batch) {
    int i = blockIdx.x * blockDim.x + threadIdx.x;
    if (i >= NN) return;
    int b = batch[i];
    if (i == 0) g_gstart[b] = 0;
    else {
        int pb = batch[i - 1];
        if (pb != b) { g_gstart[b] = i; g_gend[pb] = i - 1; }
    }
    if (i == NN - 1) g_gend[b] = NN - 1;
}

// one warp per graph: lane = (node_parity, feature)
__global__ void k_pool() {
    int w = (blockIdx.x * blockDim.x + threadIdx.x) >> 5;
    int lane = threadIdx.x & 31;
    if (w >= GG) return;
    int s = g_gstart[w], e = g_gend[w];
    int f = lane & 15, nl = lane >> 4;
    float mx = -INFINITY, sm = 0.f;
    for (int n = s + nl; n <= e; n += 2) {
        float v = g_x2[(size_t)n * DD + f];
        mx = fmaxf(mx, v);
        sm += v;
    }
    mx = fmaxf(mx, __shfl_xor_sync(0xFFFFFFFFu, mx, 16));
    sm += __shfl_xor_sync(0xFFFFFFFFu, sm, 16);
    if (lane < 16) {
        g_gmax[w * DD + f] = mx;
        g_gsum[w * DD + f] = sm;
    }
}

__global__ void k_head(const float* __restrict__ Wb, const float* __restrict__ bb,
                       const float* __restrict__ Wm, const float* __restrict__ bm,
                       float* __restrict__ out) {
    __shared__ float sWb[32 * 16];
    __shared__ float sbb[16];
    __shared__ float sWm[16];
    __shared__ float sbm;
    int t = threadIdx.x;
    for (int i = t; i < 32 * 16; i += 256) sWb[i] = tf32r(Wb[i]);
    if (t < 16) { sbb[t] = bb[t]; sWm[t] = tf32r(Wm[t]); }
    if (t == 0) sbm = bm[0];
    __syncthreads();
    int gI = blockIdx.x * blockDim.x + t;
    if (gI >= GG) return;
    float inp[32];
    float inv = 1.f / (float)(g_gend[gI] - g_gstart[gI] + 1);
    #pragma unroll
    for (int f = 0; f < 16; f++) {
        inp[f] = tf32r(g_gmax[gI * 16 + f]);
        inp[16 + f] = tf32r(g_gsum[gI * 16 + f] * inv);
    }
    float acc = sbm;
    #pragma unroll
    for (int j = 0; j < 16; j++) {
        float tt = sbb[j];
        #pragma unroll
        for (int i = 0; i < 32; i++) tt += inp[i] * sWb[i * 16 + j];
        tt = fmaxf(tt, 0.f);
        acc += tf32r(tt) * sWm[j];
    }
    out[gI] = 1.f / (1.f + expf(-acc));
}

// ---------------- launch (fork-join overlap) ----------------
extern "C" void kernel_launch(void* const* d_in, const int* in_sizes, int n_in,
                              void* d_out, int out_size) {
    const float* x   = (const float*)d_in[0];
    const int*   ei  = (const int*)d_in[1];
    const int*   bat = (const int*)d_in[2];
    const float* W1  = (const float*)d_in[3];
    const float* b1  = (const float*)d_in[4];
    const float* g1  = (const float*)d_in[5];
    const float* be1 = (const float*)d_in[6];
    const float* m1  = (const float*)d_in[7];
    const float* v1  = (const float*)d_in[8];
    const float* W2  = (const float*)d_in[9];
    const float* b2  = (const float*)d_in[10];
    const float* g2  = (const float*)d_in[11];
    const float* be2 = (const float*)d_in[12];
    const float* m2  = (const float*)d_in[13];
    const float* v2  = (const float*)d_in[14];
    const float* Wb  = (const float*)d_in[15];
    const float* bb  = (const float*)d_in[16];
    const float* Wm  = (const float*)d_in[17];
    const float* bm  = (const float*)d_in[18];
    float* out = (float*)d_out;

    const int* row = ei;
    const int* col = ei + EE;

    static cudaStream_t sB = nullptr;
    static cudaEvent_t ev0 = nullptr, evOff = nullptr, evB = nullptr;
    if (sB == nullptr) {
        cudaStreamCreateWithFlags(&sB, cudaStreamNonBlocking);
        cudaEventCreateWithFlags(&ev0, cudaEventDisableTiming);
        cudaEventCreateWithFlags(&evOff, cudaEventDisableTiming);
        cudaEventCreateWithFlags(&evB, cudaEventDisableTiming);
    }

    const int nb_n  = (NN + 255) / 256;          // 782
    const int nb_e4 = (EE / 4 + 255) / 256;      // 6250
    const int nb_2n = (NN * 2 + 255) / 256;      // 1563

    // fork: side stream does gemm1 (h), bounds, then hh1 (after offsets)
    cudaEventRecord(ev0, 0);
    cudaStreamWaitEvent(sB, ev0, 0);
    k_gemm1h<<<NN / 64, 256, 0, sB>>>(x, W1);
    k_bounds<<<nb_n, 256, 0, sB>>>(bat);

    // main stream: CSR build
    k_init<<<nb_n, 256>>>();
    k_count<<<nb_e4, 256>>>(col);
    k_offsets<<<nb_n, 256>>>();
    cudaEventRecord(evOff, 0);
    k_fill<<<nb_e4, 256>>>(row, col);

    cudaStreamWaitEvent(sB, evOff, 0);
    k_hh1<<<nb_2n, 256, 0, sB>>>();
    cudaEventRecord(evB, sB);

    // join
    cudaStreamWaitEvent(0, evB, 0);
    k_agg1<<<nb_2n, 256>>>(b1, g1, be1, m1, v1, W2);
    k_agg2<<<nb_2n, 256>>>(b2, g2, be2, m2, v2);
    k_pool<<<(GG * 32 + 255) / 256, 256>>>();
    k_head<<<(GG + 255) / 256, 256>>>(Wb, bb, Wm, bm, out);
}